// round 12
// baseline (speedup 1.0000x reference)
#include <cuda_runtime.h>
#include <cuda_bf16.h>
#include <cstdint>

#define N_ATOMS   50000
#define NUM_ELEM  10
#define LMAX      3
#define SH_DIM    16
#define CIN       128
#define COUT      128
#define TILE_M    128
#define NSEG      (NUM_ELEM * (LMAX + 1))
#define GRID_PERS 296                     // 2 CTAs per SM, persistent
#define PAN_W     20                      // fp32 words per panel row (16 + 4 pad)
#define PAN_BYTES (TILE_M * PAN_W * 4)    // 10240
#define NSTAGE    4

// SMEM layout (bytes)
#define SM_APAN   0
#define SM_BS     (NSTAGE * PAN_BYTES)            // 40960
#define SM_ROWB   (SM_BS + 65536)                 // 106496, rowb[2][128] ints
#define SM_PREFIX (SM_ROWB + 1024)                // 107520, 41 ints (pad 176)
#define SM_CNT    (SM_PREFIX + 176)               // 107696, 10 ints
#define SM_OFF    (SM_CNT + 40)                   // 107736, 10 ints
#define SMEM_BYTES (SM_OFF + 40)                  // 107776

__device__ int   g_counts[NUM_ELEM];
__device__ int   g_cursor[NUM_ELEM];
__device__ int   g_offsets[NUM_ELEM];
__device__ int   g_species[N_ATOMS];
__device__ int   g_order[N_ATOMS];
__device__ int   g_tile_prefix[NSEG + 1];
// W packed in tf32 mma B-fragment layout:
// [seg][ks16(8)][nt(16)][lane(32)] -> uint4 {s0.b0, s0.b1, s1.b0, s1.b1}
__device__ uint4 g_wpack[NSEG * 4096];

// ---------------- helpers ----------------

__device__ __forceinline__ unsigned f2tf32(float v) {
    unsigned u;
    asm("cvt.rna.tf32.f32 %0, %1;" : "=r"(u) : "f"(v));
    return u;
}

__device__ __forceinline__ void mma_tf32(float* c, unsigned a0, unsigned a1,
                                         unsigned a2, unsigned a3,
                                         unsigned b0, unsigned b1) {
    asm volatile(
        "mma.sync.aligned.m16n8k8.row.col.f32.tf32.tf32.f32 "
        "{%0,%1,%2,%3}, {%4,%5,%6,%7}, {%8,%9}, {%0,%1,%2,%3};\n"
        : "+f"(c[0]), "+f"(c[1]), "+f"(c[2]), "+f"(c[3])
        : "r"(a0), "r"(a1), "r"(a2), "r"(a3), "r"(b0), "r"(b1));
}

__device__ __forceinline__ void cp16(uint32_t dst, const void* src, int srcsize) {
    asm volatile("cp.async.cg.shared.global [%0], [%1], 16, %2;"
                 :: "r"(dst), "l"(src), "r"(srcsize));
}

// ---------------- prep kernels ----------------

__global__ void k_init() {
    int t = threadIdx.x;
    if (t < NUM_ELEM) { g_counts[t] = 0; g_cursor[t] = 0; }
}

__global__ void k_hist(const float* __restrict__ y) {
    __shared__ int cnt[NUM_ELEM];
    int tid = threadIdx.x;
    if (tid < NUM_ELEM) cnt[tid] = 0;
    __syncthreads();
    int n = blockIdx.x * blockDim.x + tid;
    if (n < N_ATOMS) {
        const float* yr = y + (long)n * NUM_ELEM;
        float best = yr[0]; int s = 0;
#pragma unroll
        for (int e = 1; e < NUM_ELEM; e++) {
            float v = yr[e];
            if (v > best) { best = v; s = e; }
        }
        g_species[n] = s;
        atomicAdd(&cnt[s], 1);
    }
    __syncthreads();
    if (tid < NUM_ELEM && cnt[tid] > 0) atomicAdd(&g_counts[tid], cnt[tid]);
}

__global__ void k_scan() {
    if (threadIdx.x == 0) {
        int off = 0;
        for (int e = 0; e < NUM_ELEM; e++) { g_offsets[e] = off; off += g_counts[e]; }
        int tp = 0, seg = 0;
        g_tile_prefix[0] = 0;
        for (int e = 0; e < NUM_ELEM; e++)
            for (int l = 0; l <= LMAX; l++) {
                int rows = g_counts[e] * (2 * l + 1);
                tp += (rows + TILE_M - 1) / TILE_M;
                g_tile_prefix[++seg] = tp;
            }
    }
}

__global__ void k_scatter() {
    __shared__ int cnt[NUM_ELEM];
    __shared__ int base[NUM_ELEM];
    int tid = threadIdx.x;
    if (tid < NUM_ELEM) cnt[tid] = 0;
    __syncthreads();
    int n = blockIdx.x * blockDim.x + tid;
    int s = -1, myrank = 0;
    if (n < N_ATOMS) {
        s = g_species[n];
        myrank = atomicAdd(&cnt[s], 1);
    }
    __syncthreads();
    if (tid < NUM_ELEM) base[tid] = cnt[tid] ? atomicAdd(&g_cursor[tid], cnt[tid]) : 0;
    __syncthreads();
    if (n < N_ATOMS) g_order[g_offsets[s] + base[s] + myrank] = n;
}

// Pack W[e][l] into tf32 mma B-fragment layout.
__global__ void k_wpack(const float* __restrict__ w) {
    int idx = blockIdx.x * blockDim.x + threadIdx.x;
    if (idx >= NSEG * 4096) return;
    int seg = idx >> 12;
    int rem = idx & 4095;
    int ks = rem >> 9;
    int nt = (rem >> 5) & 15;
    int t  = rem & 31;
    int tig = t & 3;
    int n  = nt * 8 + (t >> 2);
    const float* W = w + (long)seg * CIN * COUT;
    int k0 = ks * 16;
    unsigned b00 = f2tf32(W[(k0 + tig         ) * COUT + n]);
    unsigned b01 = f2tf32(W[(k0 + tig + 4     ) * COUT + n]);
    unsigned b10 = f2tf32(W[(k0 + 8 + tig     ) * COUT + n]);
    unsigned b11 = f2tf32(W[(k0 + 8 + tig + 4 ) * COUT + n]);
    g_wpack[idx] = make_uint4(b00, b01, b10, b11);
}

// ---------------- persistent tf32 tensor-core GEMM ----------------
// 296 persistent CTAs, ~21 segment-sorted tiles each. B resident across tiles
// of a segment. A k-panels in a 4-stage cp.async ring; prologue fills all 4
// slots; mainloop syncs once per TWO k-steps (4 barriers/tile), giving every
// panel >= 2 k-steps of flight time. Next tile's prologue issues before the
// epilogue so its DRAM ramp hides behind the stores.

__global__ __launch_bounds__(256, 2)
void k_gemm(const float* __restrict__ x, float* __restrict__ out) {
    extern __shared__ char smraw[];
    float* Apan    = (float*)(smraw + SM_APAN);     // [4][128][20]
    uint4* Bs      = (uint4*)(smraw + SM_BS);       // [8][16][32]
    int*   rowb    = (int*)(smraw + SM_ROWB);       // [2][128]
    int*   spre    = (int*)(smraw + SM_PREFIX);     // [41]
    int*   scnt    = (int*)(smraw + SM_CNT);        // [10]
    int*   soff    = (int*)(smraw + SM_OFF);        // [10]

    int tid = threadIdx.x;
    if (tid <= NSEG) spre[tid] = g_tile_prefix[tid];
    if (tid < NUM_ELEM) { scnt[tid] = g_counts[tid]; soff[tid] = g_offsets[tid]; }
    __syncthreads();

    int ntiles = spre[NSEG];
    int chunk = (ntiles + (int)gridDim.x - 1) / (int)gridDim.x;
    int t0   = blockIdx.x * chunk;
    int tend = min(t0 + chunk, ntiles);
    if (t0 >= tend) return;

    int seg = 0;
    while (spre[seg + 1] <= t0) seg++;

    int w    = tid >> 5;
    int lane = tid & 31;
    int g    = lane >> 2;
    int tig  = lane & 3;
    int mrow0 = (w & 3) * 32;       // 2 m-tiles per warp
    int ntb   = (w >> 2) * 8;       // 8 n-tiles (64 cols)

    // fixed per-thread cp.async SMEM targets: rows (tid>>2), 64+(tid>>2), quad tid&3
    int grow = tid >> 2, q = tid & 3;
    uint32_t sb = (uint32_t)__cvta_generic_to_shared(Apan);
    uint32_t d0 = sb + (grow * PAN_W + q * 4) * 4;
    uint32_t d1 = sb + ((64 + grow) * PAN_W + q * 4) * 4;

    // --- initial segment: fill B ---
    int cur_seg = seg;
    {
        const uint4* wp = g_wpack + seg * 4096;
#pragma unroll
        for (int i = 0; i < 16; i++) Bs[tid + i * 256] = wp[tid + i * 256];
    }
    // --- rowbase for tile t0 into buf 0 ---
    if (tid < TILE_M) {
        int l = seg & 3, e = seg >> 2;
        int R = 2 * l + 1;
        int r = (t0 - spre[seg]) * TILE_M + tid;
        int rb = -1;
        if (r < scnt[e] * R) {
            int atom = g_order[soff[e] + r / R];
            rb = (atom * SH_DIM + l * l + r % R) * CIN;
        }
        rowb[tid] = rb;
    }
    __syncthreads();

    // per-tile gather state (current tile)
    const float* cs0; const float* cs1; int cz0, cz1;
    {
        int rb0 = rowb[grow], rb1 = rowb[64 + grow];
        cs0 = x + (rb0 < 0 ? 0 : rb0) + q * 4;  cz0 = rb0 < 0 ? 0 : 16;
        cs1 = x + (rb1 < 0 ? 0 : rb1) + q * 4;  cz1 = rb1 < 0 ? 0 : 16;
    }
    // prologue for tile t0: fill all 4 ring slots
#pragma unroll
    for (int p = 0; p < NSTAGE; p++) {
        uint32_t off = p * PAN_BYTES;
        cp16(d0 + off, cs0 + p * 16, cz0);
        cp16(d1 + off, cs1 + p * 16, cz1);
        asm volatile("cp.async.commit_group;" ::: "memory");
    }

    float acc[2][8][4];
#pragma unroll
    for (int m = 0; m < 2; m++)
#pragma unroll
        for (int nt = 0; nt < 8; nt++)
#pragma unroll
            for (int i = 0; i < 4; i++) acc[m][nt][i] = 0.f;

    const float scale = 0.08838834764831845f;  // 1/sqrt(128)

    for (int t = t0; t < tend; t++) {
        int buf = (t - t0) & 1;
        int* rbuf = rowb + buf * TILE_M;

        // capture this tile's epilogue row offsets
        int rlo0 = rbuf[mrow0 + g],      rhi0 = rbuf[mrow0 + g + 8];
        int rlo1 = rbuf[mrow0 + 16 + g], rhi1 = rbuf[mrow0 + 16 + g + 8];

        // -------- mainloop: 8 k-steps, sync every 2 --------
#pragma unroll
        for (int ks = 0; ks < 8; ks += 2) {
            // panels ks, ks+1 must have arrived (per-thread groups)
            if (ks == 0) asm volatile("cp.async.wait_group 2;" ::: "memory");
            else         asm volatile("cp.async.wait_group 0;" ::: "memory");
            __syncthreads();   // CTA-wide visibility of panels ks, ks+1;
                               // also certifies compute of ks-2, ks-1 done
            // refill the two slots just freed (panels ks+2, ks+3)
            if (ks == 2 || ks == 4) {
#pragma unroll
                for (int p = ks + 2; p < ks + 4; p++) {
                    uint32_t off = (p & (NSTAGE - 1)) * PAN_BYTES;
                    cp16(d0 + off, cs0 + p * 16, cz0);
                    cp16(d1 + off, cs1 + p * 16, cz1);
                    asm volatile("cp.async.commit_group;" ::: "memory");
                }
            }
#pragma unroll
            for (int kk = ks; kk < ks + 2; kk++) {
                const float* A = Apan + (kk & (NSTAGE - 1)) * (PAN_BYTES / 4);
#pragma unroll
                for (int m = 0; m < 2; m++) {
                    const float* Ar0 = A + (mrow0 + m * 16 + g) * PAN_W;
                    const float* Ar1 = Ar0 + 8 * PAN_W;
                    unsigned a00 = f2tf32(Ar0[tig]);
                    unsigned a01 = f2tf32(Ar1[tig]);
                    unsigned a02 = f2tf32(Ar0[tig + 4]);
                    unsigned a03 = f2tf32(Ar1[tig + 4]);
                    unsigned a10 = f2tf32(Ar0[tig + 8]);
                    unsigned a11 = f2tf32(Ar1[tig + 8]);
                    unsigned a12 = f2tf32(Ar0[tig + 12]);
                    unsigned a13 = f2tf32(Ar1[tig + 12]);
#pragma unroll
                    for (int ntl = 0; ntl < 8; ntl++) {
                        uint4 B = Bs[kk * 512 + (ntb + ntl) * 32 + lane];
                        mma_tf32(acc[m][ntl], a00, a01, a02, a03, B.x, B.y);
                        mma_tf32(acc[m][ntl], a10, a11, a12, a13, B.z, B.w);
                    }
                }
            }
        }

        // -------- prepare next tile (before epilogue, to hide DRAM ramp) ----
        int havenext = (t + 1 < tend);
        int nseg = seg;
        if (havenext) {
            while (spre[nseg + 1] <= t + 1) nseg++;
            if (tid < TILE_M) {
                int l = nseg & 3, e = nseg >> 2;
                int R = 2 * l + 1;
                int r = (t + 1 - spre[nseg]) * TILE_M + tid;
                int rb = -1;
                if (r < scnt[e] * R) {
                    int atom = g_order[soff[e] + r / R];
                    rb = (atom * SH_DIM + l * l + r % R) * CIN;
                }
                rowb[(buf ^ 1) * TILE_M + tid] = rb;
            }
        }
        __syncthreads();   // rowbase visible; all warps past mainloop (B, Apan free)

        if (havenext && nseg != cur_seg) {
            const uint4* wp = g_wpack + nseg * 4096;
#pragma unroll
            for (int i = 0; i < 16; i++) Bs[tid + i * 256] = wp[tid + i * 256];
            cur_seg = nseg;
            __syncthreads();
        }

        if (havenext) {
            int* nbuf = rowb + (buf ^ 1) * TILE_M;
            int rb0 = nbuf[grow], rb1 = nbuf[64 + grow];
            cs0 = x + (rb0 < 0 ? 0 : rb0) + q * 4;  cz0 = rb0 < 0 ? 0 : 16;
            cs1 = x + (rb1 < 0 ? 0 : rb1) + q * 4;  cz1 = rb1 < 0 ? 0 : 16;
#pragma unroll
            for (int p = 0; p < NSTAGE; p++) {
                uint32_t off = p * PAN_BYTES;
                cp16(d0 + off, cs0 + p * 16, cz0);
                cp16(d1 + off, cs1 + p * 16, cz1);
                asm volatile("cp.async.commit_group;" ::: "memory");
            }
        }

        // -------- epilogue for tile t (overlaps next tile's prefetch) -------
#pragma unroll
        for (int m = 0; m < 2; m++) {
            int rlo = (m == 0) ? rlo0 : rlo1;
            int rhi = (m == 0) ? rhi0 : rhi1;
#pragma unroll
            for (int ntl = 0; ntl < 8; ntl++) {
                int col = (ntb + ntl) * 8 + 2 * tig;
                if (rlo >= 0)
                    *(float2*)(out + rlo + col) =
                        make_float2(acc[m][ntl][0] * scale, acc[m][ntl][1] * scale);
                if (rhi >= 0)
                    *(float2*)(out + rhi + col) =
                        make_float2(acc[m][ntl][2] * scale, acc[m][ntl][3] * scale);
                acc[m][ntl][0] = 0.f; acc[m][ntl][1] = 0.f;
                acc[m][ntl][2] = 0.f; acc[m][ntl][3] = 0.f;
            }
        }
        seg = nseg;
    }
}

// ---------------- launch ----------------

extern "C" void kernel_launch(void* const* d_in, const int* in_sizes, int n_in,
                              void* d_out, int out_size) {
    const float* x = (const float*)d_in[0];   // [N, 16, 128]
    const float* y = (const float*)d_in[1];   // [N, 10]
    const float* w = (const float*)d_in[2];   // [10, 4, 128, 128]
    float* out = (float*)d_out;               // [N, 16, 128]

    cudaFuncSetAttribute(k_gemm, cudaFuncAttributeMaxDynamicSharedMemorySize,
                         SMEM_BYTES);

    k_init<<<1, 32>>>();
    k_hist<<<(N_ATOMS + 255) / 256, 256>>>(y);
    k_scan<<<1, 32>>>();
    k_scatter<<<(N_ATOMS + 255) / 256, 256>>>();
    k_wpack<<<(NSEG * 4096 + 255) / 256, 256>>>(w);
    k_gemm<<<GRID_PERS, 256, SMEM_BYTES>>>(x, out);
}

// round 13
// speedup vs baseline: 1.0923x; 1.0923x over previous
#include <cuda_runtime.h>
#include <cuda_bf16.h>
#include <cstdint>

#define N_ATOMS   50000
#define NUM_ELEM  10
#define LMAX      3
#define SH_DIM    16
#define CIN       128
#define COUT      128
#define TILE_M    128
#define NSEG      (NUM_ELEM * (LMAX + 1))
#define GRID_PERS 296                     // 2 CTAs per SM, persistent
#define PAN_W     20                      // fp32 words per panel row (16 + 4 pad)
#define PAN_BYTES (TILE_M * PAN_W * 4)    // 10240
#define NSTAGE    4

// SMEM layout (bytes)
#define SM_APAN   0
#define SM_BS     (NSTAGE * PAN_BYTES)            // 40960
#define SM_ROWB   (SM_BS + 65536)                 // 106496, rowb[2][128] ints
#define SM_PREFIX (SM_ROWB + 1024)                // 107520, 41 ints (pad 176)
#define SM_CNT    (SM_PREFIX + 176)               // 107696, 10 ints
#define SM_OFF    (SM_CNT + 40)                   // 107736, 10 ints
#define SMEM_BYTES (SM_OFF + 40)                  // 107776

__device__ int   g_counts[NUM_ELEM];
__device__ int   g_cursor[NUM_ELEM];
__device__ int   g_offsets[NUM_ELEM];
__device__ int   g_species[N_ATOMS];
__device__ int   g_order[N_ATOMS];
__device__ int   g_tile_prefix[NSEG + 1];
// W packed in tf32 mma B-fragment layout:
// [seg][ks16(8)][nt(16)][lane(32)] -> uint4 {s0.b0, s0.b1, s1.b0, s1.b1}
__device__ uint4 g_wpack[NSEG * 4096];

// ---------------- helpers ----------------

__device__ __forceinline__ unsigned f2tf32(float v) {
    unsigned u;
    asm("cvt.rna.tf32.f32 %0, %1;" : "=r"(u) : "f"(v));
    return u;
}

__device__ __forceinline__ void mma_tf32(float* c, unsigned a0, unsigned a1,
                                         unsigned a2, unsigned a3,
                                         unsigned b0, unsigned b1) {
    asm volatile(
        "mma.sync.aligned.m16n8k8.row.col.f32.tf32.tf32.f32 "
        "{%0,%1,%2,%3}, {%4,%5,%6,%7}, {%8,%9}, {%0,%1,%2,%3};\n"
        : "+f"(c[0]), "+f"(c[1]), "+f"(c[2]), "+f"(c[3])
        : "r"(a0), "r"(a1), "r"(a2), "r"(a3), "r"(b0), "r"(b1));
}

__device__ __forceinline__ void cp16(uint32_t dst, const void* src, int srcsize) {
    asm volatile("cp.async.cg.shared.global [%0], [%1], 16, %2;"
                 :: "r"(dst), "l"(src), "r"(srcsize));
}

// ---------------- prep kernels ----------------

__global__ void k_init() {
    int t = threadIdx.x;
    if (t < NUM_ELEM) { g_counts[t] = 0; g_cursor[t] = 0; }
}

__global__ void k_hist(const float* __restrict__ y) {
    __shared__ int cnt[NUM_ELEM];
    int tid = threadIdx.x;
    if (tid < NUM_ELEM) cnt[tid] = 0;
    __syncthreads();
    int n = blockIdx.x * blockDim.x + tid;
    if (n < N_ATOMS) {
        const float* yr = y + (long)n * NUM_ELEM;
        float best = yr[0]; int s = 0;
#pragma unroll
        for (int e = 1; e < NUM_ELEM; e++) {
            float v = yr[e];
            if (v > best) { best = v; s = e; }
        }
        g_species[n] = s;
        atomicAdd(&cnt[s], 1);
    }
    __syncthreads();
    if (tid < NUM_ELEM && cnt[tid] > 0) atomicAdd(&g_counts[tid], cnt[tid]);
}

__global__ void k_scan() {
    if (threadIdx.x == 0) {
        int off = 0;
        for (int e = 0; e < NUM_ELEM; e++) { g_offsets[e] = off; off += g_counts[e]; }
        int tp = 0, seg = 0;
        g_tile_prefix[0] = 0;
        for (int e = 0; e < NUM_ELEM; e++)
            for (int l = 0; l <= LMAX; l++) {
                int rows = g_counts[e] * (2 * l + 1);
                tp += (rows + TILE_M - 1) / TILE_M;
                g_tile_prefix[++seg] = tp;
            }
    }
}

__global__ void k_scatter() {
    __shared__ int cnt[NUM_ELEM];
    __shared__ int base[NUM_ELEM];
    int tid = threadIdx.x;
    if (tid < NUM_ELEM) cnt[tid] = 0;
    __syncthreads();
    int n = blockIdx.x * blockDim.x + tid;
    int s = -1, myrank = 0;
    if (n < N_ATOMS) {
        s = g_species[n];
        myrank = atomicAdd(&cnt[s], 1);
    }
    __syncthreads();
    if (tid < NUM_ELEM) base[tid] = cnt[tid] ? atomicAdd(&g_cursor[tid], cnt[tid]) : 0;
    __syncthreads();
    if (n < N_ATOMS) g_order[g_offsets[s] + base[s] + myrank] = n;
}

// Pack W[e][l] into tf32 mma B-fragment layout.
__global__ void k_wpack(const float* __restrict__ w) {
    int idx = blockIdx.x * blockDim.x + threadIdx.x;
    if (idx >= NSEG * 4096) return;
    int seg = idx >> 12;
    int rem = idx & 4095;
    int ks = rem >> 9;
    int nt = (rem >> 5) & 15;
    int t  = rem & 31;
    int tig = t & 3;
    int n  = nt * 8 + (t >> 2);
    const float* W = w + (long)seg * CIN * COUT;
    int k0 = ks * 16;
    unsigned b00 = f2tf32(W[(k0 + tig         ) * COUT + n]);
    unsigned b01 = f2tf32(W[(k0 + tig + 4     ) * COUT + n]);
    unsigned b10 = f2tf32(W[(k0 + 8 + tig     ) * COUT + n]);
    unsigned b11 = f2tf32(W[(k0 + 8 + tig + 4 ) * COUT + n]);
    g_wpack[idx] = make_uint4(b00, b01, b10, b11);
}

// ---------------- persistent tf32 tensor-core GEMM ----------------
// 296 persistent CTAs, ~21 segment-sorted tiles each. B resident across tiles
// of a segment; A k-panels in a 4-stage cp.async ring (prefetch distance 3,
// one barrier per k-step — the R11 winner). Epilogue pairs adjacent n-tiles
// via one bfly shuffle so quads store 64 contiguous bytes per row (STG.128,
// 2x wavefront payload). Next tile's prologue issues before the epilogue.

__global__ __launch_bounds__(256, 2)
void k_gemm(const float* __restrict__ x, float* __restrict__ out) {
    extern __shared__ char smraw[];
    float* Apan    = (float*)(smraw + SM_APAN);     // [4][128][20]
    uint4* Bs      = (uint4*)(smraw + SM_BS);       // [8][16][32]
    int*   rowb    = (int*)(smraw + SM_ROWB);       // [2][128]
    int*   spre    = (int*)(smraw + SM_PREFIX);     // [41]
    int*   scnt    = (int*)(smraw + SM_CNT);        // [10]
    int*   soff    = (int*)(smraw + SM_OFF);        // [10]

    int tid = threadIdx.x;
    if (tid <= NSEG) spre[tid] = g_tile_prefix[tid];
    if (tid < NUM_ELEM) { scnt[tid] = g_counts[tid]; soff[tid] = g_offsets[tid]; }
    __syncthreads();

    int ntiles = spre[NSEG];
    int q_  = ntiles / (int)gridDim.x;
    int r_  = ntiles % (int)gridDim.x;
    int bid = blockIdx.x;
    int t0   = bid * q_ + min(bid, r_);
    int tend = t0 + q_ + (bid < r_ ? 1 : 0);
    if (t0 >= tend) return;

    int seg = 0;
    while (spre[seg + 1] <= t0) seg++;

    int w    = tid >> 5;
    int lane = tid & 31;
    int g    = lane >> 2;
    int tig  = lane & 3;
    int mrow0 = (w & 3) * 32;       // 2 m-tiles per warp
    int ntb   = (w >> 2) * 8;       // 8 n-tiles (64 cols)
    int odd   = tig & 1;

    // fixed per-thread cp.async SMEM targets: rows (tid>>2), 64+(tid>>2), quad tid&3
    int grow = tid >> 2, q = tid & 3;
    uint32_t sb = (uint32_t)__cvta_generic_to_shared(Apan);
    uint32_t d0 = sb + (grow * PAN_W + q * 4) * 4;
    uint32_t d1 = sb + ((64 + grow) * PAN_W + q * 4) * 4;

    // --- initial segment: fill B ---
    int cur_seg = seg;
    {
        const uint4* wp = g_wpack + seg * 4096;
#pragma unroll
        for (int i = 0; i < 16; i++) Bs[tid + i * 256] = wp[tid + i * 256];
    }
    // --- rowbase for tile t0 into buf 0 ---
    if (tid < TILE_M) {
        int l = seg & 3, e = seg >> 2;
        int R = 2 * l + 1;
        int r = (t0 - spre[seg]) * TILE_M + tid;
        int rb = -1;
        if (r < scnt[e] * R) {
            int atom = g_order[soff[e] + r / R];
            rb = (atom * SH_DIM + l * l + r % R) * CIN;
        }
        rowb[tid] = rb;
    }
    __syncthreads();

    // per-tile gather state (current tile)
    const float* cs0; const float* cs1; int cz0, cz1;
    {
        int rb0 = rowb[grow], rb1 = rowb[64 + grow];
        cs0 = x + (rb0 < 0 ? 0 : rb0) + q * 4;  cz0 = rb0 < 0 ? 0 : 16;
        cs1 = x + (rb1 < 0 ? 0 : rb1) + q * 4;  cz1 = rb1 < 0 ? 0 : 16;
    }
    // prologue for tile t0: panels 0..2
#pragma unroll
    for (int p = 0; p < NSTAGE - 1; p++) {
        uint32_t off = p * PAN_BYTES;
        cp16(d0 + off, cs0 + p * 16, cz0);
        cp16(d1 + off, cs1 + p * 16, cz1);
        asm volatile("cp.async.commit_group;" ::: "memory");
    }

    float acc[2][8][4];
#pragma unroll
    for (int m = 0; m < 2; m++)
#pragma unroll
        for (int nt = 0; nt < 8; nt++)
#pragma unroll
            for (int i = 0; i < 4; i++) acc[m][nt][i] = 0.f;

    const float scale = 0.08838834764831845f;  // 1/sqrt(128)

    for (int t = t0; t < tend; t++) {
        int buf = (t - t0) & 1;
        int* rbuf = rowb + buf * TILE_M;

        // capture this tile's epilogue row offsets
        int rlo0 = rbuf[mrow0 + g],      rhi0 = rbuf[mrow0 + g + 8];
        int rlo1 = rbuf[mrow0 + 16 + g], rhi1 = rbuf[mrow0 + 16 + g + 8];

        // -------- mainloop: 8 k-steps (R11 schedule) --------
#pragma unroll
        for (int ks = 0; ks < 8; ks++) {
            if (ks < 6)       asm volatile("cp.async.wait_group 2;" ::: "memory");
            else if (ks == 6) asm volatile("cp.async.wait_group 1;" ::: "memory");
            else              asm volatile("cp.async.wait_group 0;" ::: "memory");
            __syncthreads();
            if (ks < 5) {   // keep prefetch distance 3 within this tile
                uint32_t off = ((ks + 3) & (NSTAGE - 1)) * PAN_BYTES;
                cp16(d0 + off, cs0 + (ks + 3) * 16, cz0);
                cp16(d1 + off, cs1 + (ks + 3) * 16, cz1);
                asm volatile("cp.async.commit_group;" ::: "memory");
            }
            const float* A = Apan + (ks & (NSTAGE - 1)) * (PAN_BYTES / 4);
#pragma unroll
            for (int m = 0; m < 2; m++) {
                const float* Ar0 = A + (mrow0 + m * 16 + g) * PAN_W;
                const float* Ar1 = Ar0 + 8 * PAN_W;
                unsigned a00 = f2tf32(Ar0[tig]);
                unsigned a01 = f2tf32(Ar1[tig]);
                unsigned a02 = f2tf32(Ar0[tig + 4]);
                unsigned a03 = f2tf32(Ar1[tig + 4]);
                unsigned a10 = f2tf32(Ar0[tig + 8]);
                unsigned a11 = f2tf32(Ar1[tig + 8]);
                unsigned a12 = f2tf32(Ar0[tig + 12]);
                unsigned a13 = f2tf32(Ar1[tig + 12]);
#pragma unroll
                for (int ntl = 0; ntl < 8; ntl++) {
                    uint4 B = Bs[ks * 512 + (ntb + ntl) * 32 + lane];
                    mma_tf32(acc[m][ntl], a00, a01, a02, a03, B.x, B.y);
                    mma_tf32(acc[m][ntl], a10, a11, a12, a13, B.z, B.w);
                }
            }
        }

        // -------- prepare next tile (before epilogue, to hide DRAM ramp) ----
        int havenext = (t + 1 < tend);
        int nseg = seg;
        if (havenext) {
            while (spre[nseg + 1] <= t + 1) nseg++;
            if (tid < TILE_M) {
                int l = nseg & 3, e = nseg >> 2;
                int R = 2 * l + 1;
                int r = (t + 1 - spre[nseg]) * TILE_M + tid;
                int rb = -1;
                if (r < scnt[e] * R) {
                    int atom = g_order[soff[e] + r / R];
                    rb = (atom * SH_DIM + l * l + r % R) * CIN;
                }
                rowb[(buf ^ 1) * TILE_M + tid] = rb;
            }
        }
        __syncthreads();   // rowbase visible; all warps past mainloop (B, Apan free)

        if (havenext && nseg != cur_seg) {
            const uint4* wp = g_wpack + nseg * 4096;
#pragma unroll
            for (int i = 0; i < 16; i++) Bs[tid + i * 256] = wp[tid + i * 256];
            cur_seg = nseg;
            __syncthreads();
        }

        if (havenext) {
            int* nbuf = rowb + (buf ^ 1) * TILE_M;
            int rb0 = nbuf[grow], rb1 = nbuf[64 + grow];
            cs0 = x + (rb0 < 0 ? 0 : rb0) + q * 4;  cz0 = rb0 < 0 ? 0 : 16;
            cs1 = x + (rb1 < 0 ? 0 : rb1) + q * 4;  cz1 = rb1 < 0 ? 0 : 16;
#pragma unroll
            for (int p = 0; p < NSTAGE - 1; p++) {
                uint32_t off = p * PAN_BYTES;
                cp16(d0 + off, cs0 + p * 16, cz0);
                cp16(d1 + off, cs1 + p * 16, cz1);
                asm volatile("cp.async.commit_group;" ::: "memory");
            }
        }

        // -------- epilogue for tile t: paired-n-tile STG.128 ---------------
        // lanes t, t^1 swap one float2 so each lane holds 4 consecutive cols
        // of ONE n-tile; a quad then covers 64 contiguous bytes of its row.
#pragma unroll
        for (int m = 0; m < 2; m++) {
            int rlo = (m == 0) ? rlo0 : rlo1;
            int rhi = (m == 0) ? rhi0 : rhi1;
#pragma unroll
            for (int p = 0; p < 4; p++) {
                float* a0 = acc[m][2 * p];      // my frag of n-tile 2p
                float* a1 = acc[m][2 * p + 1];  // my frag of n-tile 2p+1
                // column base for this lane's STG.128 (same for both halves)
                int col = (ntb + 2 * p + odd) * 8 + (tig >> 1) * 4;
#pragma unroll
                for (int h = 0; h < 2; h++) {   // h=0: row rlo, h=1: row rhi
                    int row = h ? rhi : rlo;
                    float sx = (odd ? a0[2 * h] : a1[2 * h]) * scale;
                    float sy = (odd ? a0[2 * h + 1] : a1[2 * h + 1]) * scale;
                    float rx = __shfl_xor_sync(0xffffffffu, sx, 1);
                    float ry = __shfl_xor_sync(0xffffffffu, sy, 1);
                    float4 v;
                    if (odd) { v.x = rx; v.y = ry;
                               v.z = a1[2 * h] * scale; v.w = a1[2 * h + 1] * scale; }
                    else     { v.x = a0[2 * h] * scale; v.y = a0[2 * h + 1] * scale;
                               v.z = rx; v.w = ry; }
                    if (row >= 0) *(float4*)(out + row + col) = v;
                }
                // clear for next tile
                a0[0] = a0[1] = a0[2] = a0[3] = 0.f;
                a1[0] = a1[1] = a1[2] = a1[3] = 0.f;
            }
        }
        seg = nseg;
    }
}

// ---------------- launch ----------------

extern "C" void kernel_launch(void* const* d_in, const int* in_sizes, int n_in,
                              void* d_out, int out_size) {
    const float* x = (const float*)d_in[0];   // [N, 16, 128]
    const float* y = (const float*)d_in[1];   // [N, 10]
    const float* w = (const float*)d_in[2];   // [10, 4, 128, 128]
    float* out = (float*)d_out;               // [N, 16, 128]

    cudaFuncSetAttribute(k_gemm, cudaFuncAttributeMaxDynamicSharedMemorySize,
                         SMEM_BYTES);

    k_init<<<1, 32>>>();
    k_hist<<<(N_ATOMS + 255) / 256, 256>>>(y);
    k_scan<<<1, 32>>>();
    k_scatter<<<(N_ATOMS + 255) / 256, 256>>>();
    k_wpack<<<(NSEG * 4096 + 255) / 256, 256>>>(w);
    k_gemm<<<GRID_PERS, 256, SMEM_BYTES>>>(x, out);
}

// round 14
// speedup vs baseline: 1.1005x; 1.0075x over previous
#include <cuda_runtime.h>
#include <cuda_bf16.h>
#include <cstdint>

#define N_ATOMS   50000
#define NUM_ELEM  10
#define LMAX      3
#define SH_DIM    16
#define CIN       128
#define COUT      128
#define TILE_M    128
#define NSEG      (NUM_ELEM * (LMAX + 1))
#define GRID_PERS 296                     // 2 CTAs per SM, persistent
#define PAN_W     20                      // fp32 words per panel row (16 + 4 pad)
#define PAN_BYTES (TILE_M * PAN_W * 4)    // 10240
#define NSTAGE    4

// SMEM layout (bytes)
#define SM_APAN   0
#define SM_BS     (NSTAGE * PAN_BYTES)            // 40960
#define SM_PREFIX (SM_BS + 65536)                 // 106496, 41 ints
#define SM_CNT    (SM_PREFIX + 176)               // 106672
#define SM_OFF    (SM_CNT + 40)                   // 106712
#define SMEM_BYTES (SM_OFF + 40)                  // 106752

__device__ int   g_counts[NUM_ELEM];
__device__ int   g_cursor[NUM_ELEM];
__device__ int   g_offsets[NUM_ELEM];
__device__ int   g_species[N_ATOMS];
__device__ int   g_order[N_ATOMS];
__device__ int   g_tile_prefix[NSEG + 1];
// W packed in tf32 mma B-fragment layout, PRE-SCALED by 1/sqrt(128):
// [seg][ks16(8)][nt(16)][lane(32)] -> uint4 {s0.b0, s0.b1, s1.b0, s1.b1}
__device__ uint4 g_wpack[NSEG * 4096];

// ---------------- helpers ----------------

__device__ __forceinline__ unsigned f2tf32(float v) {
    unsigned u;
    asm("cvt.rna.tf32.f32 %0, %1;" : "=r"(u) : "f"(v));
    return u;
}

__device__ __forceinline__ void mma_tf32(float* c, unsigned a0, unsigned a1,
                                         unsigned a2, unsigned a3,
                                         unsigned b0, unsigned b1) {
    asm volatile(
        "mma.sync.aligned.m16n8k8.row.col.f32.tf32.tf32.f32 "
        "{%0,%1,%2,%3}, {%4,%5,%6,%7}, {%8,%9}, {%0,%1,%2,%3};\n"
        : "+f"(c[0]), "+f"(c[1]), "+f"(c[2]), "+f"(c[3])
        : "r"(a0), "r"(a1), "r"(a2), "r"(a3), "r"(b0), "r"(b1));
}

__device__ __forceinline__ void cp16(uint32_t dst, const void* src, int srcsize) {
    asm volatile("cp.async.cg.shared.global [%0], [%1], 16, %2;"
                 :: "r"(dst), "l"(src), "r"(srcsize));
}

// magic multipliers for unsigned division by R = 2l+1 via (r*M)>>22
__device__ __forceinline__ unsigned magicM(int l) {
    return (l == 0) ? 4194304u : (l == 1) ? 1398102u
         : (l == 2) ? 838861u  : 599187u;
}

// row base offset in x/out for logical segment-row r (or -1 if OOB)
__device__ __forceinline__ int rowfor(int r, int Mseg, int l, int offe,
                                      unsigned M, int R) {
    if (r >= Mseg) return -1;
    unsigned q = (unsigned)(((unsigned long long)(unsigned)r * M) >> 22);
    int rem = r - (int)(q * (unsigned)R);
    int atom = g_order[offe + (int)q];
    return (atom * SH_DIM + l * l + rem) * CIN;
}

// ---------------- prep kernels ----------------

__global__ void k_init() {
    int t = threadIdx.x;
    if (t < NUM_ELEM) { g_counts[t] = 0; g_cursor[t] = 0; }
}

__global__ void k_hist(const float* __restrict__ y) {
    __shared__ int cnt[NUM_ELEM];
    int tid = threadIdx.x;
    if (tid < NUM_ELEM) cnt[tid] = 0;
    __syncthreads();
    int n = blockIdx.x * blockDim.x + tid;
    if (n < N_ATOMS) {
        const float* yr = y + (long)n * NUM_ELEM;
        float best = yr[0]; int s = 0;
#pragma unroll
        for (int e = 1; e < NUM_ELEM; e++) {
            float v = yr[e];
            if (v > best) { best = v; s = e; }
        }
        g_species[n] = s;
        atomicAdd(&cnt[s], 1);
    }
    __syncthreads();
    if (tid < NUM_ELEM && cnt[tid] > 0) atomicAdd(&g_counts[tid], cnt[tid]);
}

__global__ void k_scan() {
    if (threadIdx.x == 0) {
        int off = 0;
        for (int e = 0; e < NUM_ELEM; e++) { g_offsets[e] = off; off += g_counts[e]; }
        int tp = 0, seg = 0;
        g_tile_prefix[0] = 0;
        for (int e = 0; e < NUM_ELEM; e++)
            for (int l = 0; l <= LMAX; l++) {
                int rows = g_counts[e] * (2 * l + 1);
                tp += (rows + TILE_M - 1) / TILE_M;
                g_tile_prefix[++seg] = tp;
            }
    }
}

__global__ void k_scatter() {
    __shared__ int cnt[NUM_ELEM];
    __shared__ int base[NUM_ELEM];
    int tid = threadIdx.x;
    if (tid < NUM_ELEM) cnt[tid] = 0;
    __syncthreads();
    int n = blockIdx.x * blockDim.x + tid;
    int s = -1, myrank = 0;
    if (n < N_ATOMS) {
        s = g_species[n];
        myrank = atomicAdd(&cnt[s], 1);
    }
    __syncthreads();
    if (tid < NUM_ELEM) base[tid] = cnt[tid] ? atomicAdd(&g_cursor[tid], cnt[tid]) : 0;
    __syncthreads();
    if (n < N_ATOMS) g_order[g_offsets[s] + base[s] + myrank] = n;
}

// Pack W[e][l] into tf32 mma B-fragment layout, pre-scaled by 1/sqrt(128).
__global__ void k_wpack(const float* __restrict__ w) {
    int idx = blockIdx.x * blockDim.x + threadIdx.x;
    if (idx >= NSEG * 4096) return;
    int seg = idx >> 12;
    int rem = idx & 4095;
    int ks = rem >> 9;
    int nt = (rem >> 5) & 15;
    int t  = rem & 31;
    int tig = t & 3;
    int n  = nt * 8 + (t >> 2);
    const float scale = 0.08838834764831845f;
    const float* W = w + (long)seg * CIN * COUT;
    int k0 = ks * 16;
    unsigned b00 = f2tf32(scale * W[(k0 + tig         ) * COUT + n]);
    unsigned b01 = f2tf32(scale * W[(k0 + tig + 4     ) * COUT + n]);
    unsigned b10 = f2tf32(scale * W[(k0 + 8 + tig     ) * COUT + n]);
    unsigned b11 = f2tf32(scale * W[(k0 + 8 + tig + 4 ) * COUT + n]);
    g_wpack[idx] = make_uint4(b00, b01, b10, b11);
}

// ---------------- persistent tf32 tensor-core GEMM ----------------
// 296 persistent CTAs. Per-thread rowbase (magic division, no SMEM phase, no
// extra barriers). Steady-state pipeline: at ks5/6/7 the NEXT tile's panels
// p0/p1/p2 commit into the slot freed one barrier earlier, so every k-step
// uses a uniform wait_group 2 and the cross-tile prologue ramp vanishes.
// A operand fed as raw fp32 bits (tf32 HW ignores low mantissa bits); W is
// pre-scaled in the pack, so the epilogue is pure shuffles + STG.128.

__global__ __launch_bounds__(256, 2)
void k_gemm(const float* __restrict__ x, float* __restrict__ out) {
    extern __shared__ char smraw[];
    float* Apan = (float*)(smraw + SM_APAN);     // [4][128][20]
    uint4* Bs   = (uint4*)(smraw + SM_BS);       // [8][16][32]
    int*   spre = (int*)(smraw + SM_PREFIX);     // [41]
    int*   scnt = (int*)(smraw + SM_CNT);        // [10]
    int*   soff = (int*)(smraw + SM_OFF);        // [10]

    int tid = threadIdx.x;
    if (tid <= NSEG) spre[tid] = g_tile_prefix[tid];
    if (tid < NUM_ELEM) { scnt[tid] = g_counts[tid]; soff[tid] = g_offsets[tid]; }
    __syncthreads();

    int ntiles = spre[NSEG];
    int q_  = ntiles / (int)gridDim.x;
    int r_  = ntiles % (int)gridDim.x;
    int bid = blockIdx.x;
    int t0   = bid * q_ + min(bid, r_);
    int tend = t0 + q_ + (bid < r_ ? 1 : 0);
    if (t0 >= tend) return;

    int seg = 0;
    while (spre[seg + 1] <= t0) seg++;

    int w    = tid >> 5;
    int lane = tid & 31;
    int g    = lane >> 2;
    int tig  = lane & 3;
    int mrow0 = (w & 3) * 32;       // 2 m-tiles per warp
    int ntb   = (w >> 2) * 8;       // 8 n-tiles (64 cols)
    int odd   = tig & 1;

    // fixed per-thread cp.async SMEM targets: rows (tid>>2), 64+(tid>>2), quad tid&3
    int grow = tid >> 2, q = tid & 3;
    uint32_t sb = (uint32_t)__cvta_generic_to_shared(Apan);
    uint32_t d0 = sb + (grow * PAN_W + q * 4) * 4;
    uint32_t d1 = sb + ((64 + grow) * PAN_W + q * 4) * 4;

    // --- initial segment: fill B ---
    int cur_seg = seg;
    {
        const uint4* wp = g_wpack + seg * 4096;
#pragma unroll
        for (int i = 0; i < 16; i++) Bs[tid + i * 256] = wp[tid + i * 256];
    }
    __syncthreads();

    // --- tile t0: per-thread cp rows + prologue p0..p2 ---
    const float* cs0; const float* cs1; int cz0, cz1;
    {
        int l = seg & 3, e = seg >> 2;
        int R = 2 * l + 1;
        unsigned M = magicM(l);
        int Mseg = scnt[e] * R, offe = soff[e];
        int rbase = (t0 - spre[seg]) * TILE_M;
        int rb0 = rowfor(rbase + grow,      Mseg, l, offe, M, R);
        int rb1 = rowfor(rbase + 64 + grow, Mseg, l, offe, M, R);
        cs0 = x + (rb0 < 0 ? 0 : rb0) + q * 4;  cz0 = rb0 < 0 ? 0 : 16;
        cs1 = x + (rb1 < 0 ? 0 : rb1) + q * 4;  cz1 = rb1 < 0 ? 0 : 16;
    }
#pragma unroll
    for (int p = 0; p < NSTAGE - 1; p++) {
        uint32_t off = p * PAN_BYTES;
        cp16(d0 + off, cs0 + p * 16, cz0);
        cp16(d1 + off, cs1 + p * 16, cz1);
        asm volatile("cp.async.commit_group;" ::: "memory");
    }

    float acc[2][8][4];
#pragma unroll
    for (int m = 0; m < 2; m++)
#pragma unroll
        for (int nt = 0; nt < 8; nt++)
#pragma unroll
            for (int i = 0; i < 4; i++) acc[m][nt][i] = 0.f;

    for (int t = t0; t < tend; t++) {
        int havenext = (t + 1 < tend);

        // ---- per-thread tile-start work (independent of mainloop start) ----
        int l = seg & 3, e = seg >> 2;
        int R = 2 * l + 1;
        unsigned M = magicM(l);
        int Mseg = scnt[e] * R, offe = soff[e];
        int rbase = (t - spre[seg]) * TILE_M;
        // epilogue rows for this thread
        int rlo0 = rowfor(rbase + mrow0 + g,      Mseg, l, offe, M, R);
        int rhi0 = rowfor(rbase + mrow0 + g + 8,  Mseg, l, offe, M, R);
        int rlo1 = rowfor(rbase + mrow0 + 16 + g, Mseg, l, offe, M, R);
        int rhi1 = rowfor(rbase + mrow0 + 24 + g, Mseg, l, offe, M, R);
        // next tile: segment + cp rows (needed from ks5)
        int nseg = seg;
        const float* ns0 = cs0; const float* ns1 = cs1; int nz0 = cz0, nz1 = cz1;
        if (havenext) {
            while (spre[nseg + 1] <= t + 1) nseg++;
            int nl = nseg & 3, ne = nseg >> 2;
            int nR = 2 * nl + 1;
            unsigned nM = magicM(nl);
            int nMseg = scnt[ne] * nR, noffe = soff[ne];
            int nrbase = (t + 1 - spre[nseg]) * TILE_M;
            int rb0 = rowfor(nrbase + grow,      nMseg, nl, noffe, nM, nR);
            int rb1 = rowfor(nrbase + 64 + grow, nMseg, nl, noffe, nM, nR);
            ns0 = x + (rb0 < 0 ? 0 : rb0) + q * 4;  nz0 = rb0 < 0 ? 0 : 16;
            ns1 = x + (rb1 < 0 ? 0 : rb1) + q * 4;  nz1 = rb1 < 0 ? 0 : 16;
        }

        // -------- mainloop: 8 k-steps, uniform steady-state pipeline --------
#pragma unroll
        for (int ks = 0; ks < 8; ks++) {
            if (havenext || ks < 6)
                asm volatile("cp.async.wait_group 2;" ::: "memory");
            else if (ks == 6)
                asm volatile("cp.async.wait_group 1;" ::: "memory");
            else
                asm volatile("cp.async.wait_group 0;" ::: "memory");
            __syncthreads();   // panel ks visible; prior compute certified
            if (ks < 5) {          // this tile's panel ks+3
                uint32_t off = ((ks + 3) & (NSTAGE - 1)) * PAN_BYTES;
                cp16(d0 + off, cs0 + (ks + 3) * 16, cz0);
                cp16(d1 + off, cs1 + (ks + 3) * 16, cz1);
                asm volatile("cp.async.commit_group;" ::: "memory");
            } else if (havenext) { // next tile's panel ks-5 into freed slot
                int p = ks - 5;
                uint32_t off = (p & (NSTAGE - 1)) * PAN_BYTES;
                cp16(d0 + off, ns0 + p * 16, nz0);
                cp16(d1 + off, ns1 + p * 16, nz1);
                asm volatile("cp.async.commit_group;" ::: "memory");
            }
            const unsigned* A = (const unsigned*)Apan
                              + (ks & (NSTAGE - 1)) * (PAN_BYTES / 4);
#pragma unroll
            for (int m = 0; m < 2; m++) {
                const unsigned* Ar0 = A + (mrow0 + m * 16 + g) * PAN_W;
                const unsigned* Ar1 = Ar0 + 8 * PAN_W;
                unsigned a00 = Ar0[tig];        // raw fp32 bits as tf32
                unsigned a01 = Ar1[tig];
                unsigned a02 = Ar0[tig + 4];
                unsigned a03 = Ar1[tig + 4];
                unsigned a10 = Ar0[tig + 8];
                unsigned a11 = Ar1[tig + 8];
                unsigned a12 = Ar0[tig + 12];
                unsigned a13 = Ar1[tig + 12];
#pragma unroll
                for (int ntl = 0; ntl < 8; ntl++) {
                    uint4 B = Bs[ks * 512 + (ntb + ntl) * 32 + lane];
                    mma_tf32(acc[m][ntl], a00, a01, a02, a03, B.x, B.y);
                    mma_tf32(acc[m][ntl], a10, a11, a12, a13, B.z, B.w);
                }
            }
        }

        // -------- epilogue: paired-n-tile STG.128 (scale pre-folded) --------
#pragma unroll
        for (int m = 0; m < 2; m++) {
            int rlo = (m == 0) ? rlo0 : rlo1;
            int rhi = (m == 0) ? rhi0 : rhi1;
#pragma unroll
            for (int p = 0; p < 4; p++) {
                float* a0 = acc[m][2 * p];
                float* a1 = acc[m][2 * p + 1];
                int col = (ntb + 2 * p + odd) * 8 + (tig >> 1) * 4;
#pragma unroll
                for (int h = 0; h < 2; h++) {
                    int row = h ? rhi : rlo;
                    float sx = odd ? a0[2 * h]     : a1[2 * h];
                    float sy = odd ? a0[2 * h + 1] : a1[2 * h + 1];
                    float rx = __shfl_xor_sync(0xffffffffu, sx, 1);
                    float ry = __shfl_xor_sync(0xffffffffu, sy, 1);
                    float4 v;
                    if (odd) { v.x = rx; v.y = ry; v.z = a1[2 * h]; v.w = a1[2 * h + 1]; }
                    else     { v.x = a0[2 * h]; v.y = a0[2 * h + 1]; v.z = rx; v.w = ry; }
                    if (row >= 0) *(float4*)(out + row + col) = v;
                }
                a0[0] = a0[1] = a0[2] = a0[3] = 0.f;
                a1[0] = a1[1] = a1[2] = a1[3] = 0.f;
            }
        }

        // -------- segment boundary: refill B (rare) --------
        if (havenext && nseg != cur_seg) {
            __syncthreads();   // all warps done reading old B (mainloop ks7)
            const uint4* wp = g_wpack + nseg * 4096;
#pragma unroll
            for (int i = 0; i < 16; i++) Bs[tid + i * 256] = wp[tid + i * 256];
            cur_seg = nseg;
            // visibility to all warps is certified by ks0's __syncthreads
        }
        seg = nseg;
        cs0 = ns0; cs1 = ns1; cz0 = nz0; cz1 = nz1;
    }
}

// ---------------- launch ----------------

extern "C" void kernel_launch(void* const* d_in, const int* in_sizes, int n_in,
                              void* d_out, int out_size) {
    const float* x = (const float*)d_in[0];   // [N, 16, 128]
    const float* y = (const float*)d_in[1];   // [N, 10]
    const float* w = (const float*)d_in[2];   // [10, 4, 128, 128]
    float* out = (float*)d_out;               // [N, 16, 128]

    cudaFuncSetAttribute(k_gemm, cudaFuncAttributeMaxDynamicSharedMemorySize,
                         SMEM_BYTES);

    k_init<<<1, 32>>>();
    k_hist<<<(N_ATOMS + 255) / 256, 256>>>(y);
    k_scan<<<1, 32>>>();
    k_scatter<<<(N_ATOMS + 255) / 256, 256>>>();
    k_wpack<<<(NSEG * 4096 + 255) / 256, 256>>>(w);
    k_gemm<<<GRID_PERS, 256, SMEM_BYTES>>>(x, out);
}

// round 15
// speedup vs baseline: 1.1952x; 1.0861x over previous
#include <cuda_runtime.h>
#include <cuda_bf16.h>
#include <cstdint>

#define N_ATOMS   50000
#define NUM_ELEM  10
#define LMAX      3
#define SH_DIM    16
#define CIN       128
#define COUT      128
#define TILE_M    128
#define NSEG      (NUM_ELEM * (LMAX + 1))
#define GRID_PERS 296                     // 2 CTAs per SM, persistent
#define THREADS   128                     // 4 warps, 64x64 warp tiles
#define PAN_W     20                      // fp32 words per panel row (16 + 4 pad)
#define PAN_BYTES (TILE_M * PAN_W * 4)    // 10240
#define NSTAGE    4

// SMEM layout (bytes)
#define SM_APAN   0
#define SM_BS     (NSTAGE * PAN_BYTES)            // 40960
#define SM_PREFIX (SM_BS + 65536)                 // 106496, 41 ints
#define SM_CNT    (SM_PREFIX + 176)               // 106672
#define SM_OFF    (SM_CNT + 40)                   // 106712
#define SMEM_BYTES (SM_OFF + 40)                  // 106752

__device__ int   g_counts[NUM_ELEM];
__device__ int   g_cursor[NUM_ELEM];
__device__ int   g_offsets[NUM_ELEM];
__device__ int   g_species[N_ATOMS];
__device__ int   g_order[N_ATOMS];
__device__ int   g_tile_prefix[NSEG + 1];
// W packed in tf32 mma B-fragment layout, PRE-SCALED by 1/sqrt(128):
// [seg][ks16(8)][nt(16)][lane(32)] -> uint4 {s0.b0, s0.b1, s1.b0, s1.b1}
__device__ uint4 g_wpack[NSEG * 4096];

// ---------------- helpers ----------------

__device__ __forceinline__ unsigned f2tf32(float v) {
    unsigned u;
    asm("cvt.rna.tf32.f32 %0, %1;" : "=r"(u) : "f"(v));
    return u;
}

__device__ __forceinline__ void mma_tf32(float* c, unsigned a0, unsigned a1,
                                         unsigned a2, unsigned a3,
                                         unsigned b0, unsigned b1) {
    asm volatile(
        "mma.sync.aligned.m16n8k8.row.col.f32.tf32.tf32.f32 "
        "{%0,%1,%2,%3}, {%4,%5,%6,%7}, {%8,%9}, {%0,%1,%2,%3};\n"
        : "+f"(c[0]), "+f"(c[1]), "+f"(c[2]), "+f"(c[3])
        : "r"(a0), "r"(a1), "r"(a2), "r"(a3), "r"(b0), "r"(b1));
}

__device__ __forceinline__ void cp16(uint32_t dst, const void* src, int srcsize) {
    asm volatile("cp.async.cg.shared.global [%0], [%1], 16, %2;"
                 :: "r"(dst), "l"(src), "r"(srcsize));
}

// magic multipliers for unsigned division by R = 2l+1 via (r*M)>>22
__device__ __forceinline__ unsigned magicM(int l) {
    return (l == 0) ? 4194304u : (l == 1) ? 1398102u
         : (l == 2) ? 838861u  : 599187u;
}

// row base offset in x/out for logical segment-row r (or -1 if OOB)
__device__ __forceinline__ int rowfor(int r, int Mseg, int l, int offe,
                                      unsigned M, int R) {
    if (r >= Mseg) return -1;
    unsigned q = (unsigned)(((unsigned long long)(unsigned)r * M) >> 22);
    int rem = r - (int)(q * (unsigned)R);
    int atom = g_order[offe + (int)q];
    return (atom * SH_DIM + l * l + rem) * CIN;
}

// ---------------- prep kernels ----------------

__global__ void k_init() {
    int t = threadIdx.x;
    if (t < NUM_ELEM) { g_counts[t] = 0; g_cursor[t] = 0; }
}

__global__ void k_hist(const float* __restrict__ y) {
    __shared__ int cnt[NUM_ELEM];
    int tid = threadIdx.x;
    if (tid < NUM_ELEM) cnt[tid] = 0;
    __syncthreads();
    int n = blockIdx.x * blockDim.x + tid;
    if (n < N_ATOMS) {
        const float* yr = y + (long)n * NUM_ELEM;
        float best = yr[0]; int s = 0;
#pragma unroll
        for (int e = 1; e < NUM_ELEM; e++) {
            float v = yr[e];
            if (v > best) { best = v; s = e; }
        }
        g_species[n] = s;
        atomicAdd(&cnt[s], 1);
    }
    __syncthreads();
    if (tid < NUM_ELEM && cnt[tid] > 0) atomicAdd(&g_counts[tid], cnt[tid]);
}

__global__ void k_scan() {
    if (threadIdx.x == 0) {
        int off = 0;
        for (int e = 0; e < NUM_ELEM; e++) { g_offsets[e] = off; off += g_counts[e]; }
        int tp = 0, seg = 0;
        g_tile_prefix[0] = 0;
        for (int e = 0; e < NUM_ELEM; e++)
            for (int l = 0; l <= LMAX; l++) {
                int rows = g_counts[e] * (2 * l + 1);
                tp += (rows + TILE_M - 1) / TILE_M;
                g_tile_prefix[++seg] = tp;
            }
    }
}

__global__ void k_scatter() {
    __shared__ int cnt[NUM_ELEM];
    __shared__ int base[NUM_ELEM];
    int tid = threadIdx.x;
    if (tid < NUM_ELEM) cnt[tid] = 0;
    __syncthreads();
    int n = blockIdx.x * blockDim.x + tid;
    int s = -1, myrank = 0;
    if (n < N_ATOMS) {
        s = g_species[n];
        myrank = atomicAdd(&cnt[s], 1);
    }
    __syncthreads();
    if (tid < NUM_ELEM) base[tid] = cnt[tid] ? atomicAdd(&g_cursor[tid], cnt[tid]) : 0;
    __syncthreads();
    if (n < N_ATOMS) g_order[g_offsets[s] + base[s] + myrank] = n;
}

// Pack W[e][l] into tf32 mma B-fragment layout, pre-scaled by 1/sqrt(128).
__global__ void k_wpack(const float* __restrict__ w) {
    int idx = blockIdx.x * blockDim.x + threadIdx.x;
    if (idx >= NSEG * 4096) return;
    int seg = idx >> 12;
    int rem = idx & 4095;
    int ks = rem >> 9;
    int nt = (rem >> 5) & 15;
    int t  = rem & 31;
    int tig = t & 3;
    int n  = nt * 8 + (t >> 2);
    const float scale = 0.08838834764831845f;
    const float* W = w + (long)seg * CIN * COUT;
    int k0 = ks * 16;
    unsigned b00 = f2tf32(scale * W[(k0 + tig         ) * COUT + n]);
    unsigned b01 = f2tf32(scale * W[(k0 + tig + 4     ) * COUT + n]);
    unsigned b10 = f2tf32(scale * W[(k0 + 8 + tig     ) * COUT + n]);
    unsigned b11 = f2tf32(scale * W[(k0 + 8 + tig + 4 ) * COUT + n]);
    g_wpack[idx] = make_uint4(b00, b01, b10, b11);
}

// ---------------- persistent tf32 tensor-core GEMM ----------------
// 296 persistent CTAs of 128 threads (4 warps). Warp w: m-half (w&1)*64 rows
// (4 m-tiles), n-half (w>>1)*64 cols (8 n-tiles) -> 64x64 warp tile, 128 acc
// regs. Each B fragment feeds 8 MMAs (4 m-tiles), cutting SMEM operand
// wavefronts 33% vs the 32x64 layout. Steady-state cross-tile cp.async ring
// and per-thread magic-div rowbase carried over from R14.

__global__ __launch_bounds__(THREADS, 2)
void k_gemm(const float* __restrict__ x, float* __restrict__ out) {
    extern __shared__ char smraw[];
    float* Apan = (float*)(smraw + SM_APAN);     // [4][128][20]
    uint4* Bs   = (uint4*)(smraw + SM_BS);       // [8][16][32]
    int*   spre = (int*)(smraw + SM_PREFIX);     // [41]
    int*   scnt = (int*)(smraw + SM_CNT);        // [10]
    int*   soff = (int*)(smraw + SM_OFF);        // [10]

    int tid = threadIdx.x;
    if (tid <= NSEG) spre[tid] = g_tile_prefix[tid];
    if (tid < NUM_ELEM) { scnt[tid] = g_counts[tid]; soff[tid] = g_offsets[tid]; }
    __syncthreads();

    int ntiles = spre[NSEG];
    int q_  = ntiles / (int)gridDim.x;
    int r_  = ntiles % (int)gridDim.x;
    int bid = blockIdx.x;
    int t0   = bid * q_ + min(bid, r_);
    int tend = t0 + q_ + (bid < r_ ? 1 : 0);
    if (t0 >= tend) return;

    int seg = 0;
    while (spre[seg + 1] <= t0) seg++;

    int w    = tid >> 5;
    int lane = tid & 31;
    int g    = lane >> 2;
    int tig  = lane & 3;
    int mbase = (w & 1) * 64;       // 4 m-tiles per warp (64 rows)
    int ntb   = (w >> 1) * 8;       // 8 n-tiles (64 cols)
    int odd   = tig & 1;

    // per-thread cp.async: rows grow+32j (j<4), col-quad q (16B each)
    int grow = tid >> 2, q = tid & 3;
    uint32_t sb = (uint32_t)__cvta_generic_to_shared(Apan);
    uint32_t dj[4];
#pragma unroll
    for (int j = 0; j < 4; j++)
        dj[j] = sb + ((grow + 32 * j) * PAN_W + q * 4) * 4;

    // --- initial segment: fill B (64KB / 128 threads = 32 uint4 each) ---
    int cur_seg = seg;
    {
        const uint4* wp = g_wpack + seg * 4096;
#pragma unroll
        for (int i = 0; i < 32; i++) Bs[tid + i * 128] = wp[tid + i * 128];
    }
    __syncthreads();

    // --- tile t0: per-thread cp rows + prologue p0..p2 ---
    const float* cs[4]; int cz[4];
    {
        int l = seg & 3, e = seg >> 2;
        int R = 2 * l + 1;
        unsigned M = magicM(l);
        int Mseg = scnt[e] * R, offe = soff[e];
        int rbase = (t0 - spre[seg]) * TILE_M;
#pragma unroll
        for (int j = 0; j < 4; j++) {
            int rb = rowfor(rbase + grow + 32 * j, Mseg, l, offe, M, R);
            cs[j] = x + (rb < 0 ? 0 : rb) + q * 4;
            cz[j] = rb < 0 ? 0 : 16;
        }
    }
#pragma unroll
    for (int p = 0; p < NSTAGE - 1; p++) {
        uint32_t off = p * PAN_BYTES;
#pragma unroll
        for (int j = 0; j < 4; j++) cp16(dj[j] + off, cs[j] + p * 16, cz[j]);
        asm volatile("cp.async.commit_group;" ::: "memory");
    }

    float acc[4][8][4];
#pragma unroll
    for (int m = 0; m < 4; m++)
#pragma unroll
        for (int nt = 0; nt < 8; nt++)
#pragma unroll
            for (int i = 0; i < 4; i++) acc[m][nt][i] = 0.f;

    for (int t = t0; t < tend; t++) {
        int havenext = (t + 1 < tend);

        // ---- per-thread tile-start work ----
        int l = seg & 3, e = seg >> 2;
        int R = 2 * l + 1;
        unsigned M = magicM(l);
        int Mseg = scnt[e] * R, offe = soff[e];
        int rbase = (t - spre[seg]) * TILE_M;
        int rlo[4], rhi[4];
#pragma unroll
        for (int m = 0; m < 4; m++) {
            rlo[m] = rowfor(rbase + mbase + m * 16 + g,     Mseg, l, offe, M, R);
            rhi[m] = rowfor(rbase + mbase + m * 16 + g + 8, Mseg, l, offe, M, R);
        }
        // next tile: segment + cp rows (needed from ks5)
        int nseg = seg;
        const float* ns[4]; int nz[4];
#pragma unroll
        for (int j = 0; j < 4; j++) { ns[j] = cs[j]; nz[j] = cz[j]; }
        if (havenext) {
            while (spre[nseg + 1] <= t + 1) nseg++;
            int nl = nseg & 3, ne = nseg >> 2;
            int nR = 2 * nl + 1;
            unsigned nM = magicM(nl);
            int nMseg = scnt[ne] * nR, noffe = soff[ne];
            int nrbase = (t + 1 - spre[nseg]) * TILE_M;
#pragma unroll
            for (int j = 0; j < 4; j++) {
                int rb = rowfor(nrbase + grow + 32 * j, nMseg, nl, noffe, nM, nR);
                ns[j] = x + (rb < 0 ? 0 : rb) + q * 4;
                nz[j] = rb < 0 ? 0 : 16;
            }
        }

        // -------- mainloop: 8 k-steps, uniform steady-state pipeline --------
#pragma unroll
        for (int ks = 0; ks < 8; ks++) {
            if (havenext || ks < 6)
                asm volatile("cp.async.wait_group 2;" ::: "memory");
            else if (ks == 6)
                asm volatile("cp.async.wait_group 1;" ::: "memory");
            else
                asm volatile("cp.async.wait_group 0;" ::: "memory");
            __syncthreads();
            if (ks < 5) {          // this tile's panel ks+3
                uint32_t off = ((ks + 3) & (NSTAGE - 1)) * PAN_BYTES;
#pragma unroll
                for (int j = 0; j < 4; j++)
                    cp16(dj[j] + off, cs[j] + (ks + 3) * 16, cz[j]);
                asm volatile("cp.async.commit_group;" ::: "memory");
            } else if (havenext) { // next tile's panel ks-5
                int p = ks - 5;
                uint32_t off = (p & (NSTAGE - 1)) * PAN_BYTES;
#pragma unroll
                for (int j = 0; j < 4; j++)
                    cp16(dj[j] + off, ns[j] + p * 16, nz[j]);
                asm volatile("cp.async.commit_group;" ::: "memory");
            }
            const unsigned* A = (const unsigned*)Apan
                              + (ks & (NSTAGE - 1)) * (PAN_BYTES / 4);
            unsigned a[4][8];
#pragma unroll
            for (int m = 0; m < 4; m++) {
                const unsigned* Ar0 = A + (mbase + m * 16 + g) * PAN_W;
                const unsigned* Ar1 = Ar0 + 8 * PAN_W;
                a[m][0] = Ar0[tig];       a[m][1] = Ar1[tig];
                a[m][2] = Ar0[tig + 4];   a[m][3] = Ar1[tig + 4];
                a[m][4] = Ar0[tig + 8];   a[m][5] = Ar1[tig + 8];
                a[m][6] = Ar0[tig + 12];  a[m][7] = Ar1[tig + 12];
            }
#pragma unroll
            for (int ntl = 0; ntl < 8; ntl++) {
                uint4 B = Bs[ks * 512 + (ntb + ntl) * 32 + lane];
#pragma unroll
                for (int m = 0; m < 4; m++) {
                    mma_tf32(acc[m][ntl], a[m][0], a[m][1], a[m][2], a[m][3],
                             B.x, B.y);
                    mma_tf32(acc[m][ntl], a[m][4], a[m][5], a[m][6], a[m][7],
                             B.z, B.w);
                }
            }
        }

        // -------- epilogue: paired-n-tile STG.128 (scale pre-folded) --------
#pragma unroll
        for (int m = 0; m < 4; m++) {
#pragma unroll
            for (int p = 0; p < 4; p++) {
                float* a0 = acc[m][2 * p];
                float* a1 = acc[m][2 * p + 1];
                int col = (ntb + 2 * p + odd) * 8 + (tig >> 1) * 4;
#pragma unroll
                for (int h = 0; h < 2; h++) {
                    int row = h ? rhi[m] : rlo[m];
                    float sx = odd ? a0[2 * h]     : a1[2 * h];
                    float sy = odd ? a0[2 * h + 1] : a1[2 * h + 1];
                    float rx = __shfl_xor_sync(0xffffffffu, sx, 1);
                    float ry = __shfl_xor_sync(0xffffffffu, sy, 1);
                    float4 v;
                    if (odd) { v.x = rx; v.y = ry; v.z = a1[2 * h]; v.w = a1[2 * h + 1]; }
                    else     { v.x = a0[2 * h]; v.y = a0[2 * h + 1]; v.z = rx; v.w = ry; }
                    if (row >= 0) *(float4*)(out + row + col) = v;
                }
                a0[0] = a0[1] = a0[2] = a0[3] = 0.f;
                a1[0] = a1[1] = a1[2] = a1[3] = 0.f;
            }
        }

        // -------- segment boundary: refill B (rare) --------
        if (havenext && nseg != cur_seg) {
            __syncthreads();   // all warps done reading old B
            const uint4* wp = g_wpack + nseg * 4096;
#pragma unroll
            for (int i = 0; i < 32; i++) Bs[tid + i * 128] = wp[tid + i * 128];
            cur_seg = nseg;
            // visibility certified by next tile's ks0 __syncthreads
        }
        seg = nseg;
#pragma unroll
        for (int j = 0; j < 4; j++) { cs[j] = ns[j]; cz[j] = nz[j]; }
    }
}

// ---------------- launch ----------------

extern "C" void kernel_launch(void* const* d_in, const int* in_sizes, int n_in,
                              void* d_out, int out_size) {
    const float* x = (const float*)d_in[0];   // [N, 16, 128]
    const float* y = (const float*)d_in[1];   // [N, 10]
    const float* w = (const float*)d_in[2];   // [10, 4, 128, 128]
    float* out = (float*)d_out;               // [N, 16, 128]

    cudaFuncSetAttribute(k_gemm, cudaFuncAttributeMaxDynamicSharedMemorySize,
                         SMEM_BYTES);

    k_init<<<1, 32>>>();
    k_hist<<<(N_ATOMS + 255) / 256, 256>>>(y);
    k_scan<<<1, 32>>>();
    k_scatter<<<(N_ATOMS + 255) / 256, 256>>>();
    k_wpack<<<(NSEG * 4096 + 255) / 256, 256>>>(w);
    k_gemm<<<GRID_PERS, THREADS, SMEM_BYTES>>>(x, out);
}

// round 16
// speedup vs baseline: 1.2097x; 1.0122x over previous
#include <cuda_runtime.h>
#include <cuda_bf16.h>
#include <cstdint>

#define N_ATOMS   50000
#define NUM_ELEM  10
#define LMAX      3
#define SH_DIM    16
#define CIN       128
#define COUT      128
#define TILE_M    128
#define NSEG      (NUM_ELEM * (LMAX + 1))
#define GRID_PERS 296                     // 2 CTAs per SM, persistent
#define THREADS   128                     // 4 warps, 64x64 warp tiles
#define PAN_W     20                      // fp32 words per panel row (16 + 4 pad)
#define PAN_BYTES (TILE_M * PAN_W * 4)    // 10240
#define NSTAGE    4
#define HBLK      196                     // hist blocks (256 thr each)
#define WBLK      640                     // wpack blocks

// SMEM layout (bytes)
#define SM_APAN   0
#define SM_BS     (NSTAGE * PAN_BYTES)            // 40960
#define SM_PREFIX (SM_BS + 65536)                 // 106496, 41 ints
#define SM_CNT    (SM_PREFIX + 176)               // 106672
#define SM_OFF    (SM_CNT + 40)                   // 106712
#define SMEM_BYTES (SM_OFF + 40)                  // 106752

__device__ int   g_counts[NUM_ELEM];
__device__ int   g_offsets[NUM_ELEM];
__device__ int   g_species[N_ATOMS];
__device__ int   g_rank[N_ATOMS];
__device__ int   g_order[N_ATOMS];
__device__ int   g_pcnt[HBLK * NUM_ELEM];
__device__ int   g_pbase[HBLK * NUM_ELEM];
__device__ int   g_tile_prefix[NSEG + 1];
// W packed in tf32 mma B-fragment layout, PRE-SCALED by 1/sqrt(128):
// [seg][ks16(8)][nt(16)][lane(32)] -> uint4 {s0.b0, s0.b1, s1.b0, s1.b1}
__device__ uint4 g_wpack[NSEG * 4096];

// ---------------- helpers ----------------

__device__ __forceinline__ unsigned f2tf32(float v) {
    unsigned u;
    asm("cvt.rna.tf32.f32 %0, %1;" : "=r"(u) : "f"(v));
    return u;
}

__device__ __forceinline__ void mma_tf32(float* c, unsigned a0, unsigned a1,
                                         unsigned a2, unsigned a3,
                                         unsigned b0, unsigned b1) {
    asm volatile(
        "mma.sync.aligned.m16n8k8.row.col.f32.tf32.tf32.f32 "
        "{%0,%1,%2,%3}, {%4,%5,%6,%7}, {%8,%9}, {%0,%1,%2,%3};\n"
        : "+f"(c[0]), "+f"(c[1]), "+f"(c[2]), "+f"(c[3])
        : "r"(a0), "r"(a1), "r"(a2), "r"(a3), "r"(b0), "r"(b1));
}

__device__ __forceinline__ void cp16(uint32_t dst, const void* src, int srcsize) {
    asm volatile("cp.async.cg.shared.global [%0], [%1], 16, %2;"
                 :: "r"(dst), "l"(src), "r"(srcsize));
}

// magic multipliers for unsigned division by R = 2l+1 via (r*M)>>22
__device__ __forceinline__ unsigned magicM(int l) {
    return (l == 0) ? 4194304u : (l == 1) ? 1398102u
         : (l == 2) ? 838861u  : 599187u;
}

// row base offset in x/out for logical segment-row r (or -1 if OOB)
__device__ __forceinline__ int rowfor(int r, int Mseg, int l, int offe,
                                      unsigned M, int R) {
    if (r >= Mseg) return -1;
    unsigned q = (unsigned)(((unsigned long long)(unsigned)r * M) >> 22);
    int rem = r - (int)(q * (unsigned)R);
    int atom = g_order[offe + (int)q];
    return (atom * SH_DIM + l * l + rem) * CIN;
}

// ---------------- prep kernels (3 launches total) ----------------

// Blocks 0..HBLK-1: per-block histogram (partial counts + local rank, no
// global atomics). Blocks HBLK..HBLK+WBLK-1: W fragment pack (independent).
__global__ void k_prep(const float* __restrict__ y, const float* __restrict__ w) {
    int tid = threadIdx.x;
    if (blockIdx.x < HBLK) {
        __shared__ int cnt[NUM_ELEM];
        if (tid < NUM_ELEM) cnt[tid] = 0;
        __syncthreads();
        int n = blockIdx.x * 256 + tid;
        if (n < N_ATOMS) {
            const float* yr = y + (long)n * NUM_ELEM;
            float best = yr[0]; int s = 0;
#pragma unroll
            for (int e = 1; e < NUM_ELEM; e++) {
                float v = yr[e];
                if (v > best) { best = v; s = e; }
            }
            g_species[n] = s;
            g_rank[n] = atomicAdd(&cnt[s], 1);
        }
        __syncthreads();
        if (tid < NUM_ELEM) g_pcnt[blockIdx.x * NUM_ELEM + tid] = cnt[tid];
    } else {
        int idx = (blockIdx.x - HBLK) * 256 + tid;
        if (idx >= NSEG * 4096) return;
        int seg = idx >> 12;
        int rem = idx & 4095;
        int ks = rem >> 9;
        int nt = (rem >> 5) & 15;
        int t  = rem & 31;
        int tig = t & 3;
        int n  = nt * 8 + (t >> 2);
        const float scale = 0.08838834764831845f;
        const float* W = w + (long)seg * CIN * COUT;
        int k0 = ks * 16;
        unsigned b00 = f2tf32(scale * W[(k0 + tig         ) * COUT + n]);
        unsigned b01 = f2tf32(scale * W[(k0 + tig + 4     ) * COUT + n]);
        unsigned b10 = f2tf32(scale * W[(k0 + 8 + tig     ) * COUT + n]);
        unsigned b11 = f2tf32(scale * W[(k0 + 8 + tig + 4 ) * COUT + n]);
        g_wpack[idx] = make_uint4(b00, b01, b10, b11);
    }
}

// One block, 10 warps: warp e scans species e's per-block partial counts into
// exclusive bases + total; thread 0 then builds offsets + tile prefix.
__global__ void k_scan() {
    int tid  = threadIdx.x;
    int w    = tid >> 5;
    int lane = tid & 31;
    if (w < NUM_ELEM) {
        int run = 0;
        for (int j = 0; j < HBLK; j += 32) {
            int b = j + lane;
            int v = (b < HBLK) ? g_pcnt[b * NUM_ELEM + w] : 0;
            int incl = v;
#pragma unroll
            for (int d = 1; d < 32; d <<= 1) {
                int t = __shfl_up_sync(0xffffffffu, incl, d);
                if (lane >= d) incl += t;
            }
            if (b < HBLK) g_pbase[b * NUM_ELEM + w] = run + incl - v;
            run += __shfl_sync(0xffffffffu, incl, 31);
        }
        if (lane == 0) g_counts[w] = run;
    }
    __syncthreads();
    if (tid == 0) {
        int off = 0;
        for (int e = 0; e < NUM_ELEM; e++) { g_offsets[e] = off; off += g_counts[e]; }
        int tp = 0, seg = 0;
        g_tile_prefix[0] = 0;
        for (int e = 0; e < NUM_ELEM; e++)
            for (int l = 0; l <= LMAX; l++) {
                int rows = g_counts[e] * (2 * l + 1);
                tp += (rows + TILE_M - 1) / TILE_M;
                g_tile_prefix[++seg] = tp;
            }
    }
}

// Pure arithmetic scatter: pos = species offset + block base + local rank.
__global__ void k_scatter() {
    int n = blockIdx.x * 256 + threadIdx.x;
    if (n >= N_ATOMS) return;
    int s = g_species[n];
    int pos = g_offsets[s] + g_pbase[(n >> 8) * NUM_ELEM + s] + g_rank[n];
    g_order[pos] = n;
}

// ---------------- persistent tf32 tensor-core GEMM (R15 winner, unchanged) --
// 296 persistent CTAs of 128 threads (4 warps). Warp w: m-half (w&1)*64 rows
// (4 m-tiles), n-half (w>>1)*64 cols (8 n-tiles) -> 64x64 warp tile.

__global__ __launch_bounds__(THREADS, 2)
void k_gemm(const float* __restrict__ x, float* __restrict__ out) {
    extern __shared__ char smraw[];
    float* Apan = (float*)(smraw + SM_APAN);     // [4][128][20]
    uint4* Bs   = (uint4*)(smraw + SM_BS);       // [8][16][32]
    int*   spre = (int*)(smraw + SM_PREFIX);     // [41]
    int*   scnt = (int*)(smraw + SM_CNT);        // [10]
    int*   soff = (int*)(smraw + SM_OFF);        // [10]

    int tid = threadIdx.x;
    if (tid <= NSEG) spre[tid] = g_tile_prefix[tid];
    if (tid < NUM_ELEM) { scnt[tid] = g_counts[tid]; soff[tid] = g_offsets[tid]; }
    __syncthreads();

    int ntiles = spre[NSEG];
    int q_  = ntiles / (int)gridDim.x;
    int r_  = ntiles % (int)gridDim.x;
    int bid = blockIdx.x;
    int t0   = bid * q_ + min(bid, r_);
    int tend = t0 + q_ + (bid < r_ ? 1 : 0);
    if (t0 >= tend) return;

    int seg = 0;
    while (spre[seg + 1] <= t0) seg++;

    int w    = tid >> 5;
    int lane = tid & 31;
    int g    = lane >> 2;
    int tig  = lane & 3;
    int mbase = (w & 1) * 64;       // 4 m-tiles per warp (64 rows)
    int ntb   = (w >> 1) * 8;       // 8 n-tiles (64 cols)
    int odd   = tig & 1;

    // per-thread cp.async: rows grow+32j (j<4), col-quad q (16B each)
    int grow = tid >> 2, q = tid & 3;
    uint32_t sb = (uint32_t)__cvta_generic_to_shared(Apan);
    uint32_t dj[4];
#pragma unroll
    for (int j = 0; j < 4; j++)
        dj[j] = sb + ((grow + 32 * j) * PAN_W + q * 4) * 4;

    // --- initial segment: fill B (64KB / 128 threads = 32 uint4 each) ---
    int cur_seg = seg;
    {
        const uint4* wp = g_wpack + seg * 4096;
#pragma unroll
        for (int i = 0; i < 32; i++) Bs[tid + i * 128] = wp[tid + i * 128];
    }
    __syncthreads();

    // --- tile t0: per-thread cp rows + prologue p0..p2 ---
    const float* cs[4]; int cz[4];
    {
        int l = seg & 3, e = seg >> 2;
        int R = 2 * l + 1;
        unsigned M = magicM(l);
        int Mseg = scnt[e] * R, offe = soff[e];
        int rbase = (t0 - spre[seg]) * TILE_M;
#pragma unroll
        for (int j = 0; j < 4; j++) {
            int rb = rowfor(rbase + grow + 32 * j, Mseg, l, offe, M, R);
            cs[j] = x + (rb < 0 ? 0 : rb) + q * 4;
            cz[j] = rb < 0 ? 0 : 16;
        }
    }
#pragma unroll
    for (int p = 0; p < NSTAGE - 1; p++) {
        uint32_t off = p * PAN_BYTES;
#pragma unroll
        for (int j = 0; j < 4; j++) cp16(dj[j] + off, cs[j] + p * 16, cz[j]);
        asm volatile("cp.async.commit_group;" ::: "memory");
    }

    float acc[4][8][4];
#pragma unroll
    for (int m = 0; m < 4; m++)
#pragma unroll
        for (int nt = 0; nt < 8; nt++)
#pragma unroll
            for (int i = 0; i < 4; i++) acc[m][nt][i] = 0.f;

    for (int t = t0; t < tend; t++) {
        int havenext = (t + 1 < tend);

        // ---- per-thread tile-start work ----
        int l = seg & 3, e = seg >> 2;
        int R = 2 * l + 1;
        unsigned M = magicM(l);
        int Mseg = scnt[e] * R, offe = soff[e];
        int rbase = (t - spre[seg]) * TILE_M;
        int rlo[4], rhi[4];
#pragma unroll
        for (int m = 0; m < 4; m++) {
            rlo[m] = rowfor(rbase + mbase + m * 16 + g,     Mseg, l, offe, M, R);
            rhi[m] = rowfor(rbase + mbase + m * 16 + g + 8, Mseg, l, offe, M, R);
        }
        // next tile: segment + cp rows (needed from ks5)
        int nseg = seg;
        const float* ns[4]; int nz[4];
#pragma unroll
        for (int j = 0; j < 4; j++) { ns[j] = cs[j]; nz[j] = cz[j]; }
        if (havenext) {
            while (spre[nseg + 1] <= t + 1) nseg++;
            int nl = nseg & 3, ne = nseg >> 2;
            int nR = 2 * nl + 1;
            unsigned nM = magicM(nl);
            int nMseg = scnt[ne] * nR, noffe = soff[ne];
            int nrbase = (t + 1 - spre[nseg]) * TILE_M;
#pragma unroll
            for (int j = 0; j < 4; j++) {
                int rb = rowfor(nrbase + grow + 32 * j, nMseg, nl, noffe, nM, nR);
                ns[j] = x + (rb < 0 ? 0 : rb) + q * 4;
                nz[j] = rb < 0 ? 0 : 16;
            }
        }

        // -------- mainloop: 8 k-steps, uniform steady-state pipeline --------
#pragma unroll
        for (int ks = 0; ks < 8; ks++) {
            if (havenext || ks < 6)
                asm volatile("cp.async.wait_group 2;" ::: "memory");
            else if (ks == 6)
                asm volatile("cp.async.wait_group 1;" ::: "memory");
            else
                asm volatile("cp.async.wait_group 0;" ::: "memory");
            __syncthreads();
            if (ks < 5) {          // this tile's panel ks+3
                uint32_t off = ((ks + 3) & (NSTAGE - 1)) * PAN_BYTES;
#pragma unroll
                for (int j = 0; j < 4; j++)
                    cp16(dj[j] + off, cs[j] + (ks + 3) * 16, cz[j]);
                asm volatile("cp.async.commit_group;" ::: "memory");
            } else if (havenext) { // next tile's panel ks-5
                int p = ks - 5;
                uint32_t off = (p & (NSTAGE - 1)) * PAN_BYTES;
#pragma unroll
                for (int j = 0; j < 4; j++)
                    cp16(dj[j] + off, ns[j] + p * 16, nz[j]);
                asm volatile("cp.async.commit_group;" ::: "memory");
            }
            const unsigned* A = (const unsigned*)Apan
                              + (ks & (NSTAGE - 1)) * (PAN_BYTES / 4);
            unsigned a[4][8];
#pragma unroll
            for (int m = 0; m < 4; m++) {
                const unsigned* Ar0 = A + (mbase + m * 16 + g) * PAN_W;
                const unsigned* Ar1 = Ar0 + 8 * PAN_W;
                a[m][0] = Ar0[tig];       a[m][1] = Ar1[tig];
                a[m][2] = Ar0[tig + 4];   a[m][3] = Ar1[tig + 4];
                a[m][4] = Ar0[tig + 8];   a[m][5] = Ar1[tig + 8];
                a[m][6] = Ar0[tig + 12];  a[m][7] = Ar1[tig + 12];
            }
#pragma unroll
            for (int ntl = 0; ntl < 8; ntl++) {
                uint4 B = Bs[ks * 512 + (ntb + ntl) * 32 + lane];
#pragma unroll
                for (int m = 0; m < 4; m++) {
                    mma_tf32(acc[m][ntl], a[m][0], a[m][1], a[m][2], a[m][3],
                             B.x, B.y);
                    mma_tf32(acc[m][ntl], a[m][4], a[m][5], a[m][6], a[m][7],
                             B.z, B.w);
                }
            }
        }

        // -------- epilogue: paired-n-tile STG.128 (scale pre-folded) --------
#pragma unroll
        for (int m = 0; m < 4; m++) {
#pragma unroll
            for (int p = 0; p < 4; p++) {
                float* a0 = acc[m][2 * p];
                float* a1 = acc[m][2 * p + 1];
                int col = (ntb + 2 * p + odd) * 8 + (tig >> 1) * 4;
#pragma unroll
                for (int h = 0; h < 2; h++) {
                    int row = h ? rhi[m] : rlo[m];
                    float sx = odd ? a0[2 * h]     : a1[2 * h];
                    float sy = odd ? a0[2 * h + 1] : a1[2 * h + 1];
                    float rx = __shfl_xor_sync(0xffffffffu, sx, 1);
                    float ry = __shfl_xor_sync(0xffffffffu, sy, 1);
                    float4 v;
                    if (odd) { v.x = rx; v.y = ry; v.z = a1[2 * h]; v.w = a1[2 * h + 1]; }
                    else     { v.x = a0[2 * h]; v.y = a0[2 * h + 1]; v.z = rx; v.w = ry; }
                    if (row >= 0) *(float4*)(out + row + col) = v;
                }
                a0[0] = a0[1] = a0[2] = a0[3] = 0.f;
                a1[0] = a1[1] = a1[2] = a1[3] = 0.f;
            }
        }

        // -------- segment boundary: refill B (rare) --------
        if (havenext && nseg != cur_seg) {
            __syncthreads();   // all warps done reading old B
            const uint4* wp = g_wpack + nseg * 4096;
#pragma unroll
            for (int i = 0; i < 32; i++) Bs[tid + i * 128] = wp[tid + i * 128];
            cur_seg = nseg;
            // visibility certified by next tile's ks0 __syncthreads
        }
        seg = nseg;
#pragma unroll
        for (int j = 0; j < 4; j++) { cs[j] = ns[j]; cz[j] = nz[j]; }
    }
}

// ---------------- launch ----------------

extern "C" void kernel_launch(void* const* d_in, const int* in_sizes, int n_in,
                              void* d_out, int out_size) {
    const float* x = (const float*)d_in[0];   // [N, 16, 128]
    const float* y = (const float*)d_in[1];   // [N, 10]
    const float* w = (const float*)d_in[2];   // [10, 4, 128, 128]
    float* out = (float*)d_out;               // [N, 16, 128]

    cudaFuncSetAttribute(k_gemm, cudaFuncAttributeMaxDynamicSharedMemorySize,
                         SMEM_BYTES);

    k_prep<<<HBLK + WBLK, 256>>>(y, w);
    k_scan<<<1, 320>>>();
    k_scatter<<<HBLK, 256>>>();
    k_gemm<<<GRID_PERS, THREADS, SMEM_BYTES>>>(x, out);
}